// round 9
// baseline (speedup 1.0000x reference)
#include <cuda_runtime.h>
#include <cstddef>

// Problem constants
#define D_MODEL 1024
#define N_HEADS 16
#define D_K     64
#define BATCH   2
#define SEQ     2048
#define MROWS   (BATCH * SEQ)              // 4096
#define OUT_ELEMS   ((size_t)MROWS * D_MODEL)              // 4,194,304
#define ATTN_ELEMS  ((size_t)BATCH * N_HEADS * SEQ * SEQ)  // 134,217,728
#define NEGINF  (-3.4e38f)

// Scratch (allocation-guard-safe: static __device__ globals)
__device__ float g_qp[MROWS * D_MODEL];
__device__ float g_kp[MROWS * D_MODEL];
__device__ float g_vp[MROWS * D_MODEL];
__device__ float g_op[MROWS * D_MODEL];
__device__ float g_attn[ATTN_ELEMS];       // fallback if harness doesn't expose attn in d_out

__device__ __forceinline__ float* attn_ptr(float* dout, int attn_in_out) {
    return attn_in_out ? (dout + OUT_ELEMS) : g_attn;
}

// ---- packed f32x2 helpers (sm_103a) ---------------------------------------
__device__ __forceinline__ unsigned long long pack2(float x, float y) {
    unsigned long long r;
    asm("mov.b64 %0, {%1, %2};" : "=l"(r) : "f"(x), "f"(y));
    return r;
}
__device__ __forceinline__ void unpack2(unsigned long long p, float& x, float& y) {
    asm("mov.b64 {%0, %1}, %2;" : "=f"(x), "=f"(y) : "l"(p));
}
__device__ __forceinline__ void ffma2(unsigned long long& d,
                                      unsigned long long a, unsigned long long b) {
    asm("fma.rn.f32x2 %0, %1, %2, %0;" : "+l"(d) : "l"(a), "l"(b));
}

// ---------------------------------------------------------------------------
// NT GEMM + bias: C[M,N] = A[M,K] @ W[N,K]^T + bias[N]
// 128x128 tile, BK=8, 256 thr, 8x8 microtile, FFMA2 mainloop,
// double-buffered smem, float4 gmem loads (LDG.128), 1 bar.sync / iter.
// csel: 0->g_qp, 1->g_kp, 2->g_vp, 3->Cext.  Aext==nullptr -> g_op.
// ---------------------------------------------------------------------------
__global__ __launch_bounds__(256) void gemm_nt_bias(
    const float* __restrict__ Aext, const float* __restrict__ W,
    const float* __restrict__ bias, float* __restrict__ Cext,
    int csel, int M, int N, int K)
{
    const float* A = Aext ? Aext : g_op;
    float* C;
    switch (csel) { case 0: C = g_qp; break; case 1: C = g_kp; break;
                    case 2: C = g_vp; break; default: C = Cext; break; }

    __shared__ float As[2][8][132];
    __shared__ float Bs[2][8][132];
    const int tid = threadIdx.x;
    const int tx = tid & 15, ty = tid >> 4;
    const int row0 = blockIdx.y * 128, col0 = blockIdx.x * 128;

    // Tile load: 128 rows x 8 k = 256 float4. Thread t: row lmr = t>>1,
    // k-offset lkk = (t&1)*4. One float4 from A, one from W per iteration.
    const int lmr = tid >> 1, lkk = (tid & 1) * 4;
    const float* Arow = A + (size_t)(row0 + lmr) * K + lkk;
    const float* Wrow = W + (size_t)(col0 + lmr) * K + lkk;

    // Preload k0 = 0
    {
        float4 va = *reinterpret_cast<const float4*>(Arow);
        float4 vb = *reinterpret_cast<const float4*>(Wrow);
        As[0][lkk+0][lmr] = va.x; As[0][lkk+1][lmr] = va.y;
        As[0][lkk+2][lmr] = va.z; As[0][lkk+3][lmr] = va.w;
        Bs[0][lkk+0][lmr] = vb.x; Bs[0][lkk+1][lmr] = vb.y;
        Bs[0][lkk+2][lmr] = vb.z; Bs[0][lkk+3][lmr] = vb.w;
    }
    __syncthreads();

    unsigned long long acc[8][4] = {};   // 8 rows x 4 col-pairs
    int buf = 0;
    for (int k0 = 0; k0 < K; k0 += 8) {
        float4 ra, rb;
        const bool more = (k0 + 8) < K;
        if (more) {
            ra = *reinterpret_cast<const float4*>(Arow + k0 + 8);
            rb = *reinterpret_cast<const float4*>(Wrow + k0 + 8);
        }
        #pragma unroll
        for (int kk = 0; kk < 8; kk++) {
            float4 a0 = *reinterpret_cast<const float4*>(&As[buf][kk][ty * 8]);
            float4 a1 = *reinterpret_cast<const float4*>(&As[buf][kk][ty * 8 + 4]);
            float4 b0 = *reinterpret_cast<const float4*>(&Bs[buf][kk][tx * 8]);
            float4 b1 = *reinterpret_cast<const float4*>(&Bs[buf][kk][tx * 8 + 4]);
            unsigned long long bp[4] = { pack2(b0.x, b0.y), pack2(b0.z, b0.w),
                                         pack2(b1.x, b1.y), pack2(b1.z, b1.w) };
            float a[8] = {a0.x,a0.y,a0.z,a0.w,a1.x,a1.y,a1.z,a1.w};
            #pragma unroll
            for (int i = 0; i < 8; i++) {
                unsigned long long ap = pack2(a[i], a[i]);
                #pragma unroll
                for (int j = 0; j < 4; j++) ffma2(acc[i][j], ap, bp[j]);
            }
        }
        if (more) {
            As[buf^1][lkk+0][lmr] = ra.x; As[buf^1][lkk+1][lmr] = ra.y;
            As[buf^1][lkk+2][lmr] = ra.z; As[buf^1][lkk+3][lmr] = ra.w;
            Bs[buf^1][lkk+0][lmr] = rb.x; Bs[buf^1][lkk+1][lmr] = rb.y;
            Bs[buf^1][lkk+2][lmr] = rb.z; Bs[buf^1][lkk+3][lmr] = rb.w;
            __syncthreads();
            buf ^= 1;
        }
    }
    #pragma unroll
    for (int i = 0; i < 8; i++) {
        int r = row0 + ty * 8 + i;
        #pragma unroll
        for (int j = 0; j < 4; j++) {
            int c = col0 + tx * 8 + 2 * j;
            float f0, f1; unpack2(acc[i][j], f0, f1);
            C[(size_t)r * N + c]     = f0 + bias[c];
            C[(size_t)r * N + c + 1] = f1 + bias[c + 1];
        }
    }
}

// ---------------------------------------------------------------------------
// Scores: per (b,h), S[i,j] = (qh_i . kh_j)/8.  Only lower-triangle tiles are
// computed/stored; masked elements are NEVER written (softmax writes the 0s).
// Double-buffered, float4 gmem loads.
// ---------------------------------------------------------------------------
__global__ __launch_bounds__(256) void scores_kernel(float* __restrict__ dout, int attn_in_out)
{
    const int row0 = blockIdx.y * 128, col0 = blockIdx.x * 128;
    if (col0 >= row0 + 128) return;        // fully above diagonal: nothing to do

    const int bh = blockIdx.z;
    const int b = bh >> 4, h = bh & 15;
    const float* A  = g_qp + (size_t)b * SEQ * D_MODEL + h * D_K;
    const float* Bm = g_kp + (size_t)b * SEQ * D_MODEL + h * D_K;
    float* C = attn_ptr(dout, attn_in_out) + (size_t)bh * SEQ * SEQ;

    const int tid = threadIdx.x;
    const int tx = tid & 15, ty = tid >> 4;

    __shared__ float As[2][8][132];
    __shared__ float Bs[2][8][132];

    const int lmr = tid >> 1, lkk = (tid & 1) * 4;
    const float* Arow = A + (size_t)(row0 + lmr) * D_MODEL + lkk;
    const float* Brow = Bm + (size_t)(col0 + lmr) * D_MODEL + lkk;

    {
        float4 va = *reinterpret_cast<const float4*>(Arow);
        float4 vb = *reinterpret_cast<const float4*>(Brow);
        As[0][lkk+0][lmr] = va.x; As[0][lkk+1][lmr] = va.y;
        As[0][lkk+2][lmr] = va.z; As[0][lkk+3][lmr] = va.w;
        Bs[0][lkk+0][lmr] = vb.x; Bs[0][lkk+1][lmr] = vb.y;
        Bs[0][lkk+2][lmr] = vb.z; Bs[0][lkk+3][lmr] = vb.w;
    }
    __syncthreads();

    unsigned long long acc[8][4] = {};
    int buf = 0;
    #pragma unroll
    for (int k0 = 0; k0 < D_K; k0 += 8) {
        float4 ra, rb;
        const bool more = (k0 + 8) < D_K;
        if (more) {
            ra = *reinterpret_cast<const float4*>(Arow + k0 + 8);
            rb = *reinterpret_cast<const float4*>(Brow + k0 + 8);
        }
        #pragma unroll
        for (int kk = 0; kk < 8; kk++) {
            float4 a0 = *reinterpret_cast<const float4*>(&As[buf][kk][ty * 8]);
            float4 a1 = *reinterpret_cast<const float4*>(&As[buf][kk][ty * 8 + 4]);
            float4 b0 = *reinterpret_cast<const float4*>(&Bs[buf][kk][tx * 8]);
            float4 b1 = *reinterpret_cast<const float4*>(&Bs[buf][kk][tx * 8 + 4]);
            unsigned long long bp[4] = { pack2(b0.x, b0.y), pack2(b0.z, b0.w),
                                         pack2(b1.x, b1.y), pack2(b1.z, b1.w) };
            float a[8] = {a0.x,a0.y,a0.z,a0.w,a1.x,a1.y,a1.z,a1.w};
            #pragma unroll
            for (int i = 0; i < 8; i++) {
                unsigned long long ap = pack2(a[i], a[i]);
                #pragma unroll
                for (int j = 0; j < 4; j++) ffma2(acc[i][j], ap, bp[j]);
            }
        }
        if (more) {
            As[buf^1][lkk+0][lmr] = ra.x; As[buf^1][lkk+1][lmr] = ra.y;
            As[buf^1][lkk+2][lmr] = ra.z; As[buf^1][lkk+3][lmr] = ra.w;
            Bs[buf^1][lkk+0][lmr] = rb.x; Bs[buf^1][lkk+1][lmr] = rb.y;
            Bs[buf^1][lkk+2][lmr] = rb.z; Bs[buf^1][lkk+3][lmr] = rb.w;
            __syncthreads();
            buf ^= 1;
        }
    }
    const float scale = 0.125f;   // 1/sqrt(64)
    #pragma unroll
    for (int i = 0; i < 8; i++) {
        int r = row0 + ty * 8 + i;
        #pragma unroll
        for (int j = 0; j < 4; j++) {
            int c = col0 + tx * 8 + 2 * j;
            float f0, f1; unpack2(acc[i][j], f0, f1);
            if (c     <= r) C[(size_t)r * SEQ + c]     = f0 * scale;
            if (c + 1 <= r) C[(size_t)r * SEQ + c + 1] = f1 * scale;
        }
    }
}

// ---------------------------------------------------------------------------
// Row softmax over 2048 cols, in place. Causal: reads only cols <= row,
// writes exact 0 above the diagonal (matches exp(-1e9 - m) == 0 in fp32).
// One block per row, 256 thr, float4 I/O, warp-shuffle reductions.
// ---------------------------------------------------------------------------
__global__ __launch_bounds__(256) void softmax_kernel(float* __restrict__ dout, int attn_in_out)
{
    const int row = blockIdx.x;
    const int bh  = blockIdx.y;
    float* p = attn_ptr(dout, attn_in_out) + (size_t)bh * SEQ * SEQ + (size_t)row * SEQ;
    float4* p4 = reinterpret_cast<float4*>(p);
    __shared__ float red[8];
    const int tid = threadIdx.x;
    const int lane = tid & 31, wid = tid >> 5;

    // 2048 floats = 512 float4; thread handles float4 idx tid and tid+256.
    float v[8];
    float m = NEGINF;
    #pragma unroll
    for (int e = 0; e < 2; e++) {
        int c4 = tid + e * 256;
        int c  = c4 * 4;
        if (c <= row) {                      // at least first lane valid
            float4 x = p4[c4];
            v[e*4+0] = x.x;
            v[e*4+1] = (c + 1 <= row) ? x.y : NEGINF;
            v[e*4+2] = (c + 2 <= row) ? x.z : NEGINF;
            v[e*4+3] = (c + 3 <= row) ? x.w : NEGINF;
        } else {
            v[e*4+0] = v[e*4+1] = v[e*4+2] = v[e*4+3] = NEGINF;
        }
        #pragma unroll
        for (int t = 0; t < 4; t++) m = fmaxf(m, v[e*4+t]);
    }
    #pragma unroll
    for (int s = 16; s > 0; s >>= 1)
        m = fmaxf(m, __shfl_xor_sync(0xFFFFFFFFu, m, s));
    if (lane == 0) red[wid] = m;
    __syncthreads();
    m = red[lane & 7];
    #pragma unroll
    for (int s = 4; s > 0; s >>= 1)
        m = fmaxf(m, __shfl_xor_sync(0xFFFFFFFFu, m, s));
    // m is now the row max in every thread

    float sum = 0.f;
    #pragma unroll
    for (int e = 0; e < 8; e++) {
        v[e] = (v[e] == NEGINF) ? 0.0f : __expf(v[e] - m);
        sum += v[e];
    }
    #pragma unroll
    for (int s = 16; s > 0; s >>= 1)
        sum += __shfl_xor_sync(0xFFFFFFFFu, sum, s);
    __syncthreads();               // protect red[] reuse
    if (lane == 0) red[wid] = sum;
    __syncthreads();
    sum = red[lane & 7];
    #pragma unroll
    for (int s = 4; s > 0; s >>= 1)
        sum += __shfl_xor_sync(0xFFFFFFFFu, sum, s);

    const float inv = 1.0f / sum;
    #pragma unroll
    for (int e = 0; e < 2; e++) {
        int c4 = tid + e * 256;
        float4 o;
        o.x = v[e*4+0] * inv;
        o.y = v[e*4+1] * inv;
        o.z = v[e*4+2] * inv;
        o.w = v[e*4+3] * inv;
        p4[c4] = o;
    }
}

// ---------------------------------------------------------------------------
// PV (NN GEMM): per (b,h), O[i,d] = sum_j attn[i,j] * vh[j,d].
// Causal k-truncation. BM=64, BN=64, BK=16, 256 thr, 4x4 microtile (FFMA2),
// double-buffered smem, float4 gmem loads. Output in [b, s, h*64+d] layout.
// ---------------------------------------------------------------------------
__global__ __launch_bounds__(256) void pv_kernel(float* __restrict__ dout, int attn_in_out)
{
    const int bh = blockIdx.z;
    const int b = bh >> 4, h = bh & 15;
    const float* A  = attn_ptr(dout, attn_in_out) + (size_t)bh * SEQ * SEQ;
    const float* Bm = g_vp + (size_t)b * SEQ * D_MODEL + h * D_K;
    float* C        = g_op + (size_t)b * SEQ * D_MODEL + h * D_K;

    __shared__ float As[2][16][68];
    __shared__ float Bs[2][16][64];
    const int tid = threadIdx.x;
    const int tx = tid & 15, ty = tid >> 4;
    const int row0 = blockIdx.y * 64;
    const int kend = row0 + 64;        // causal truncation

    // A-tile: 64 rows x 16 k = 256 float4. Thread t: row amr = t>>2, k-off akk=(t&3)*4.
    const int amr = tid >> 2, akk = (tid & 3) * 4;
    const float* Arow = A + (size_t)(row0 + amr) * SEQ + akk;
    // B-tile: thread loads float4 at row bkk = tid>>4, col bj4 = (tid&15)*4
    const int bkk = tid >> 4, bj4 = (tid & 15) * 4;

    // Preload k0 = 0
    {
        float4 va = *reinterpret_cast<const float4*>(Arow);
        As[0][akk+0][amr] = va.x; As[0][akk+1][amr] = va.y;
        As[0][akk+2][amr] = va.z; As[0][akk+3][amr] = va.w;
        float4 w = *reinterpret_cast<const float4*>(&Bm[(size_t)bkk * D_MODEL + bj4]);
        Bs[0][bkk][bj4] = w.x; Bs[0][bkk][bj4+1] = w.y; Bs[0][bkk][bj4+2] = w.z; Bs[0][bkk][bj4+3] = w.w;
    }
    __syncthreads();

    unsigned long long acc[4][2] = {};
    int buf = 0;
    for (int k0 = 0; k0 < kend; k0 += 16) {
        float4 ra, rb;
        const bool more = (k0 + 16) < kend;
        if (more) {
            ra = *reinterpret_cast<const float4*>(Arow + k0 + 16);
            rb = *reinterpret_cast<const float4*>(&Bm[(size_t)(k0 + 16 + bkk) * D_MODEL + bj4]);
        }
        #pragma unroll
        for (int kk = 0; kk < 16; kk++) {
            float4 av = *reinterpret_cast<const float4*>(&As[buf][kk][ty * 4]);
            float4 bv = *reinterpret_cast<const float4*>(&Bs[buf][kk][tx * 4]);
            unsigned long long bp[2] = { pack2(bv.x, bv.y), pack2(bv.z, bv.w) };
            float a[4] = {av.x, av.y, av.z, av.w};
            #pragma unroll
            for (int i = 0; i < 4; i++) {
                unsigned long long ap = pack2(a[i], a[i]);
                ffma2(acc[i][0], ap, bp[0]);
                ffma2(acc[i][1], ap, bp[1]);
            }
        }
        if (more) {
            As[buf^1][akk+0][amr] = ra.x; As[buf^1][akk+1][amr] = ra.y;
            As[buf^1][akk+2][amr] = ra.z; As[buf^1][akk+3][amr] = ra.w;
            Bs[buf^1][bkk][bj4] = rb.x; Bs[buf^1][bkk][bj4+1] = rb.y;
            Bs[buf^1][bkk][bj4+2] = rb.z; Bs[buf^1][bkk][bj4+3] = rb.w;
            __syncthreads();
            buf ^= 1;
        }
    }
    #pragma unroll
    for (int i = 0; i < 4; i++) {
        int r = row0 + ty * 4 + i;
        float f0, f1, f2, f3;
        unpack2(acc[i][0], f0, f1);
        unpack2(acc[i][1], f2, f3);
        float* cp = &C[(size_t)r * D_MODEL + tx * 4];
        cp[0] = f0; cp[1] = f1; cp[2] = f2; cp[3] = f3;
    }
}

// ---------------------------------------------------------------------------
extern "C" void kernel_launch(void* const* d_in, const int* in_sizes, int n_in,
                              void* d_out, int out_size)
{
    const float* q   = (const float*)d_in[0];
    const float* k   = (const float*)d_in[1];
    const float* v   = (const float*)d_in[2];
    // d_in[3] = causal mask (bool) — structure known, unused
    const float* w_q = (const float*)d_in[4];
    const float* b_q = (const float*)d_in[5];
    const float* w_k = (const float*)d_in[6];
    const float* b_k = (const float*)d_in[7];
    const float* w_v = (const float*)d_in[8];
    const float* b_v = (const float*)d_in[9];
    const float* w_o = (const float*)d_in[10];
    const float* b_o = (const float*)d_in[11];
    float* out = (float*)d_out;

    // If the harness output holds (out, attn_weights) concatenated, write attn
    // straight into d_out; otherwise use the __device__ scratch.
    const int attn_in_out = ((size_t)out_size >= OUT_ELEMS + ATTN_ELEMS) ? 1 : 0;

    dim3 thr(256);
    // Projections: [4096,1024] = X @ W^T + b
    dim3 gproj(D_MODEL / 128, MROWS / 128);
    gemm_nt_bias<<<gproj, thr>>>(q, w_q, b_q, nullptr, 0, MROWS, D_MODEL, D_MODEL);
    gemm_nt_bias<<<gproj, thr>>>(k, w_k, b_k, nullptr, 1, MROWS, D_MODEL, D_MODEL);
    gemm_nt_bias<<<gproj, thr>>>(v, w_v, b_v, nullptr, 2, MROWS, D_MODEL, D_MODEL);

    // Scores (lower-triangle tiles only)
    dim3 gsc(SEQ / 128, SEQ / 128, BATCH * N_HEADS);
    scores_kernel<<<gsc, thr>>>(out, attn_in_out);

    // Softmax (writes final attn_weights incl. exact zeros above diagonal)
    dim3 gsm(SEQ, BATCH * N_HEADS);
    softmax_kernel<<<gsm, thr>>>(out, attn_in_out);

    // attn @ V  ->  [b, s, h*64+d]
    dim3 gpv(1, SEQ / 64, BATCH * N_HEADS);
    pv_kernel<<<gpv, thr>>>(out, attn_in_out);

    // Output projection -> d_out[0 : 4M)
    gemm_nt_bias<<<gproj, thr>>>(nullptr, w_o, b_o, out, 3, MROWS, D_MODEL, D_MODEL);
}

// round 15
// speedup vs baseline: 1.6077x; 1.6077x over previous
#include <cuda_runtime.h>
#include <cstddef>
#include <cstdint>

// Problem constants
#define D_MODEL 1024
#define N_HEADS 16
#define D_K     64
#define BATCH   2
#define SEQ     2048
#define MROWS   (BATCH * SEQ)              // 4096
#define OUT_ELEMS   ((size_t)MROWS * D_MODEL)              // 4,194,304
#define ATTN_ELEMS  ((size_t)BATCH * N_HEADS * SEQ * SEQ)  // 134,217,728
#define NEGINF  (-3.4e38f)

// Scratch (allocation-guard-safe: static __device__ globals)
__device__ float g_qp[MROWS * D_MODEL];
__device__ float g_kp[MROWS * D_MODEL];
__device__ float g_vp[MROWS * D_MODEL];
__device__ float g_op[MROWS * D_MODEL];
__device__ float g_attn[ATTN_ELEMS];       // fallback if harness doesn't expose attn in d_out

__device__ __forceinline__ float* attn_ptr(float* dout, int attn_in_out) {
    return attn_in_out ? (dout + OUT_ELEMS) : g_attn;
}

// ---- packed f32x2 helpers (sm_103a) — still used by pv_kernel -------------
__device__ __forceinline__ unsigned long long pack2(float x, float y) {
    unsigned long long r;
    asm("mov.b64 %0, {%1, %2};" : "=l"(r) : "f"(x), "f"(y));
    return r;
}
__device__ __forceinline__ void unpack2(unsigned long long p, float& x, float& y) {
    asm("mov.b64 {%0, %1}, %2;" : "=f"(x), "=f"(y) : "l"(p));
}
__device__ __forceinline__ void ffma2(unsigned long long& d,
                                      unsigned long long a, unsigned long long b) {
    asm("fma.rn.f32x2 %0, %1, %2, %0;" : "+l"(d) : "l"(a), "l"(b));
}

// ---- tf32 mma helpers -----------------------------------------------------
__device__ __forceinline__ uint32_t f2tf(float f) {
    uint32_t u;
    asm("cvt.rna.tf32.f32 %0, %1;" : "=r"(u) : "f"(f));
    return u;
}
__device__ __forceinline__ void mma_tf32(float* c, const uint32_t* a, const uint32_t* b) {
    asm("mma.sync.aligned.m16n8k8.row.col.f32.tf32.tf32.f32 "
        "{%0,%1,%2,%3},{%4,%5,%6,%7},{%8,%9},{%0,%1,%2,%3};"
        : "+f"(c[0]), "+f"(c[1]), "+f"(c[2]), "+f"(c[3])
        : "r"(a[0]), "r"(a[1]), "r"(a[2]), "r"(a[3]), "r"(b[0]), "r"(b[1]));
}

// Smem tile pad: stride 136 words -> fragment loads (bank = 8*tig + gid) conflict-free
#define TPAD 136

// ---------------------------------------------------------------------------
// tf32 NT GEMM + bias: C[M,N] = A[M,K] @ W[N,K]^T + bias[N]
// BM=BN=128, BK=16, 256 thr (8 warps as 2x4; warp tile 64x32), m16n8k8 mma,
// double-buffered smem (k-major tiles), cvt.rna at smem-store time.
// csel: 0->g_qp, 1->g_kp, 2->g_vp, 3->Cext.  Aext==nullptr -> g_op.
// ---------------------------------------------------------------------------
__global__ __launch_bounds__(256) void gemm_nt_bias_tc(
    const float* __restrict__ Aext, const float* __restrict__ W,
    const float* __restrict__ bias, float* __restrict__ Cext,
    int csel, int M, int N, int K)
{
    const float* A = Aext ? Aext : g_op;
    float* C;
    switch (csel) { case 0: C = g_qp; break; case 1: C = g_kp; break;
                    case 2: C = g_vp; break; default: C = Cext; break; }

    __shared__ uint32_t As[2][16][TPAD];
    __shared__ uint32_t Bs[2][16][TPAD];

    const int tid  = threadIdx.x;
    const int lane = tid & 31, wid = tid >> 5;
    const int wm = wid >> 2, wn = wid & 3;          // warp grid 2x4
    const int gid = lane >> 2, tig = lane & 3;
    const int row0 = blockIdx.y * 128, col0 = blockIdx.x * 128;

    // Loader: thread t -> tile row (t>>1), k-offsets 4*(t&1) and 4*(t&1)+8
    const int lrow = tid >> 1, lk = (tid & 1) * 4;
    const float* Ap = A + (size_t)(row0 + lrow) * K + lk;
    const float* Wp = W + (size_t)(col0 + lrow) * K + lk;

    // Preload k0 = 0 into buf 0
    {
        float4 va0 = *(const float4*)(Ap);
        float4 va1 = *(const float4*)(Ap + 8);
        float4 vb0 = *(const float4*)(Wp);
        float4 vb1 = *(const float4*)(Wp + 8);
        As[0][lk+0][lrow] = f2tf(va0.x); As[0][lk+1][lrow] = f2tf(va0.y);
        As[0][lk+2][lrow] = f2tf(va0.z); As[0][lk+3][lrow] = f2tf(va0.w);
        As[0][lk+8][lrow] = f2tf(va1.x); As[0][lk+9][lrow] = f2tf(va1.y);
        As[0][lk+10][lrow] = f2tf(va1.z); As[0][lk+11][lrow] = f2tf(va1.w);
        Bs[0][lk+0][lrow] = f2tf(vb0.x); Bs[0][lk+1][lrow] = f2tf(vb0.y);
        Bs[0][lk+2][lrow] = f2tf(vb0.z); Bs[0][lk+3][lrow] = f2tf(vb0.w);
        Bs[0][lk+8][lrow] = f2tf(vb1.x); Bs[0][lk+9][lrow] = f2tf(vb1.y);
        Bs[0][lk+10][lrow] = f2tf(vb1.z); Bs[0][lk+11][lrow] = f2tf(vb1.w);
    }
    __syncthreads();

    float acc[4][4][4] = {};            // [m-frag][n-frag][c0..c3]
    int buf = 0;
    for (int k0 = 0; k0 < K; k0 += 16) {
        const bool more = (k0 + 16) < K;
        float4 va0, va1, vb0, vb1;
        if (more) {
            va0 = *(const float4*)(Ap + k0 + 16);
            va1 = *(const float4*)(Ap + k0 + 24);
            vb0 = *(const float4*)(Wp + k0 + 16);
            vb1 = *(const float4*)(Wp + k0 + 24);
        }
        #pragma unroll
        for (int ks = 0; ks < 2; ks++) {
            const int kb = ks * 8;
            uint32_t a[4][4], b[4][2];
            #pragma unroll
            for (int fm = 0; fm < 4; fm++) {
                int m = wm * 64 + fm * 16 + gid;
                a[fm][0] = As[buf][kb + tig][m];
                a[fm][1] = As[buf][kb + tig][m + 8];
                a[fm][2] = As[buf][kb + tig + 4][m];
                a[fm][3] = As[buf][kb + tig + 4][m + 8];
            }
            #pragma unroll
            for (int fn = 0; fn < 4; fn++) {
                int n = wn * 32 + fn * 8 + gid;
                b[fn][0] = Bs[buf][kb + tig][n];
                b[fn][1] = Bs[buf][kb + tig + 4][n];
            }
            #pragma unroll
            for (int fm = 0; fm < 4; fm++)
                #pragma unroll
                for (int fn = 0; fn < 4; fn++)
                    mma_tf32(acc[fm][fn], a[fm], b[fn]);
        }
        if (more) {
            int nb = buf ^ 1;
            As[nb][lk+0][lrow] = f2tf(va0.x); As[nb][lk+1][lrow] = f2tf(va0.y);
            As[nb][lk+2][lrow] = f2tf(va0.z); As[nb][lk+3][lrow] = f2tf(va0.w);
            As[nb][lk+8][lrow] = f2tf(va1.x); As[nb][lk+9][lrow] = f2tf(va1.y);
            As[nb][lk+10][lrow] = f2tf(va1.z); As[nb][lk+11][lrow] = f2tf(va1.w);
            Bs[nb][lk+0][lrow] = f2tf(vb0.x); Bs[nb][lk+1][lrow] = f2tf(vb0.y);
            Bs[nb][lk+2][lrow] = f2tf(vb0.z); Bs[nb][lk+3][lrow] = f2tf(vb0.w);
            Bs[nb][lk+8][lrow] = f2tf(vb1.x); Bs[nb][lk+9][lrow] = f2tf(vb1.y);
            Bs[nb][lk+10][lrow] = f2tf(vb1.z); Bs[nb][lk+11][lrow] = f2tf(vb1.w);
            __syncthreads();
            buf ^= 1;
        }
    }

    // Epilogue: c0/c1 at (row=gid, cols 2tig, 2tig+1); c2/c3 at row gid+8
    #pragma unroll
    for (int fm = 0; fm < 4; fm++) {
        int r = row0 + wm * 64 + fm * 16 + gid;
        #pragma unroll
        for (int fn = 0; fn < 4; fn++) {
            int c = col0 + wn * 32 + fn * 8 + tig * 2;
            float b0 = bias[c], b1 = bias[c + 1];
            C[(size_t)r * N + c]           = acc[fm][fn][0] + b0;
            C[(size_t)r * N + c + 1]       = acc[fm][fn][1] + b1;
            C[(size_t)(r + 8) * N + c]     = acc[fm][fn][2] + b0;
            C[(size_t)(r + 8) * N + c + 1] = acc[fm][fn][3] + b1;
        }
    }
}

// ---------------------------------------------------------------------------
// tf32 scores: per (b,h), S[i,j] = (qh_i . kh_j)/8, lower triangle only.
// Same mma microkernel, K = D_K = 64 (4 iters), lda = D_MODEL.
// Masked elements NEVER written (softmax writes the exact 0s).
// ---------------------------------------------------------------------------
__global__ __launch_bounds__(256) void scores_kernel_tc(float* __restrict__ dout, int attn_in_out)
{
    const int row0 = blockIdx.y * 128, col0 = blockIdx.x * 128;
    if (col0 >= row0 + 128) return;        // fully above diagonal

    const int bh = blockIdx.z;
    const int b = bh >> 4, h = bh & 15;
    const float* Aq = g_qp + (size_t)b * SEQ * D_MODEL + h * D_K;
    const float* Bk = g_kp + (size_t)b * SEQ * D_MODEL + h * D_K;
    float* C = attn_ptr(dout, attn_in_out) + (size_t)bh * SEQ * SEQ;

    __shared__ uint32_t As[2][16][TPAD];
    __shared__ uint32_t Bs[2][16][TPAD];

    const int tid  = threadIdx.x;
    const int lane = tid & 31, wid = tid >> 5;
    const int wm = wid >> 2, wn = wid & 3;
    const int gid = lane >> 2, tig = lane & 3;

    const int lrow = tid >> 1, lk = (tid & 1) * 4;
    const float* Ap = Aq + (size_t)(row0 + lrow) * D_MODEL + lk;
    const float* Bp = Bk + (size_t)(col0 + lrow) * D_MODEL + lk;

    {
        float4 va0 = *(const float4*)(Ap);
        float4 va1 = *(const float4*)(Ap + 8);
        float4 vb0 = *(const float4*)(Bp);
        float4 vb1 = *(const float4*)(Bp + 8);
        As[0][lk+0][lrow] = f2tf(va0.x); As[0][lk+1][lrow] = f2tf(va0.y);
        As[0][lk+2][lrow] = f2tf(va0.z); As[0][lk+3][lrow] = f2tf(va0.w);
        As[0][lk+8][lrow] = f2tf(va1.x); As[0][lk+9][lrow] = f2tf(va1.y);
        As[0][lk+10][lrow] = f2tf(va1.z); As[0][lk+11][lrow] = f2tf(va1.w);
        Bs[0][lk+0][lrow] = f2tf(vb0.x); Bs[0][lk+1][lrow] = f2tf(vb0.y);
        Bs[0][lk+2][lrow] = f2tf(vb0.z); Bs[0][lk+3][lrow] = f2tf(vb0.w);
        Bs[0][lk+8][lrow] = f2tf(vb1.x); Bs[0][lk+9][lrow] = f2tf(vb1.y);
        Bs[0][lk+10][lrow] = f2tf(vb1.z); Bs[0][lk+11][lrow] = f2tf(vb1.w);
    }
    __syncthreads();

    float acc[4][4][4] = {};
    int buf = 0;
    #pragma unroll
    for (int k0 = 0; k0 < D_K; k0 += 16) {
        const bool more = (k0 + 16) < D_K;
        float4 va0, va1, vb0, vb1;
        if (more) {
            va0 = *(const float4*)(Ap + k0 + 16);
            va1 = *(const float4*)(Ap + k0 + 24);
            vb0 = *(const float4*)(Bp + k0 + 16);
            vb1 = *(const float4*)(Bp + k0 + 24);
        }
        #pragma unroll
        for (int ks = 0; ks < 2; ks++) {
            const int kb = ks * 8;
            uint32_t a[4][4], bfr[4][2];
            #pragma unroll
            for (int fm = 0; fm < 4; fm++) {
                int m = wm * 64 + fm * 16 + gid;
                a[fm][0] = As[buf][kb + tig][m];
                a[fm][1] = As[buf][kb + tig][m + 8];
                a[fm][2] = As[buf][kb + tig + 4][m];
                a[fm][3] = As[buf][kb + tig + 4][m + 8];
            }
            #pragma unroll
            for (int fn = 0; fn < 4; fn++) {
                int n = wn * 32 + fn * 8 + gid;
                bfr[fn][0] = Bs[buf][kb + tig][n];
                bfr[fn][1] = Bs[buf][kb + tig + 4][n];
            }
            #pragma unroll
            for (int fm = 0; fm < 4; fm++)
                #pragma unroll
                for (int fn = 0; fn < 4; fn++)
                    mma_tf32(acc[fm][fn], a[fm], bfr[fn]);
        }
        if (more) {
            int nb = buf ^ 1;
            As[nb][lk+0][lrow] = f2tf(va0.x); As[nb][lk+1][lrow] = f2tf(va0.y);
            As[nb][lk+2][lrow] = f2tf(va0.z); As[nb][lk+3][lrow] = f2tf(va0.w);
            As[nb][lk+8][lrow] = f2tf(va1.x); As[nb][lk+9][lrow] = f2tf(va1.y);
            As[nb][lk+10][lrow] = f2tf(va1.z); As[nb][lk+11][lrow] = f2tf(va1.w);
            Bs[nb][lk+0][lrow] = f2tf(vb0.x); Bs[nb][lk+1][lrow] = f2tf(vb0.y);
            Bs[nb][lk+2][lrow] = f2tf(vb0.z); Bs[nb][lk+3][lrow] = f2tf(vb0.w);
            Bs[nb][lk+8][lrow] = f2tf(vb1.x); Bs[nb][lk+9][lrow] = f2tf(vb1.y);
            Bs[nb][lk+10][lrow] = f2tf(vb1.z); Bs[nb][lk+11][lrow] = f2tf(vb1.w);
            __syncthreads();
            buf ^= 1;
        }
    }

    const float scale = 0.125f;   // 1/sqrt(64)
    #pragma unroll
    for (int fm = 0; fm < 4; fm++) {
        int r0 = row0 + wm * 64 + fm * 16 + gid;
        int r1 = r0 + 8;
        #pragma unroll
        for (int fn = 0; fn < 4; fn++) {
            int c = col0 + wn * 32 + fn * 8 + tig * 2;
            if (c     <= r0) C[(size_t)r0 * SEQ + c]     = acc[fm][fn][0] * scale;
            if (c + 1 <= r0) C[(size_t)r0 * SEQ + c + 1] = acc[fm][fn][1] * scale;
            if (c     <= r1) C[(size_t)r1 * SEQ + c]     = acc[fm][fn][2] * scale;
            if (c + 1 <= r1) C[(size_t)r1 * SEQ + c + 1] = acc[fm][fn][3] * scale;
        }
    }
}

// ---------------------------------------------------------------------------
// Row softmax over 2048 cols, in place. Causal: reads only cols <= row,
// writes exact 0 above the diagonal. float4 I/O, warp-shuffle reductions.
// ---------------------------------------------------------------------------
__global__ __launch_bounds__(256) void softmax_kernel(float* __restrict__ dout, int attn_in_out)
{
    const int row = blockIdx.x;
    const int bh  = blockIdx.y;
    float* p = attn_ptr(dout, attn_in_out) + (size_t)bh * SEQ * SEQ + (size_t)row * SEQ;
    float4* p4 = reinterpret_cast<float4*>(p);
    __shared__ float red[8];
    const int tid = threadIdx.x;
    const int lane = tid & 31, wid = tid >> 5;

    float v[8];
    float m = NEGINF;
    #pragma unroll
    for (int e = 0; e < 2; e++) {
        int c4 = tid + e * 256;
        int c  = c4 * 4;
        if (c <= row) {
            float4 x = p4[c4];
            v[e*4+0] = x.x;
            v[e*4+1] = (c + 1 <= row) ? x.y : NEGINF;
            v[e*4+2] = (c + 2 <= row) ? x.z : NEGINF;
            v[e*4+3] = (c + 3 <= row) ? x.w : NEGINF;
        } else {
            v[e*4+0] = v[e*4+1] = v[e*4+2] = v[e*4+3] = NEGINF;
        }
        #pragma unroll
        for (int t = 0; t < 4; t++) m = fmaxf(m, v[e*4+t]);
    }
    #pragma unroll
    for (int s = 16; s > 0; s >>= 1)
        m = fmaxf(m, __shfl_xor_sync(0xFFFFFFFFu, m, s));
    if (lane == 0) red[wid] = m;
    __syncthreads();
    m = red[lane & 7];
    #pragma unroll
    for (int s = 4; s > 0; s >>= 1)
        m = fmaxf(m, __shfl_xor_sync(0xFFFFFFFFu, m, s));

    float sum = 0.f;
    #pragma unroll
    for (int e = 0; e < 8; e++) {
        v[e] = (v[e] == NEGINF) ? 0.0f : __expf(v[e] - m);
        sum += v[e];
    }
    #pragma unroll
    for (int s = 16; s > 0; s >>= 1)
        sum += __shfl_xor_sync(0xFFFFFFFFu, sum, s);
    __syncthreads();
    if (lane == 0) red[wid] = sum;
    __syncthreads();
    sum = red[lane & 7];
    #pragma unroll
    for (int s = 4; s > 0; s >>= 1)
        sum += __shfl_xor_sync(0xFFFFFFFFu, sum, s);

    const float inv = 1.0f / sum;
    #pragma unroll
    for (int e = 0; e < 2; e++) {
        int c4 = tid + e * 256;
        float4 o;
        o.x = v[e*4+0] * inv;
        o.y = v[e*4+1] * inv;
        o.z = v[e*4+2] * inv;
        o.w = v[e*4+3] * inv;
        p4[c4] = o;
    }
}

// ---------------------------------------------------------------------------
// PV (NN GEMM): per (b,h), O[i,d] = sum_j attn[i,j] * vh[j,d].
// Causal k-truncation. FFMA2, double-buffered. Memory-bound (reads attn).
// ---------------------------------------------------------------------------
__global__ __launch_bounds__(256) void pv_kernel(float* __restrict__ dout, int attn_in_out)
{
    const int bh = blockIdx.z;
    const int b = bh >> 4, h = bh & 15;
    const float* A  = attn_ptr(dout, attn_in_out) + (size_t)bh * SEQ * SEQ;
    const float* Bm = g_vp + (size_t)b * SEQ * D_MODEL + h * D_K;
    float* C        = g_op + (size_t)b * SEQ * D_MODEL + h * D_K;

    __shared__ float As[2][16][68];
    __shared__ float Bs[2][16][64];
    const int tid = threadIdx.x;
    const int tx = tid & 15, ty = tid >> 4;
    const int row0 = blockIdx.y * 64;
    const int kend = row0 + 64;

    const int amr = tid >> 2, akk = (tid & 3) * 4;
    const float* Arow = A + (size_t)(row0 + amr) * SEQ + akk;
    const int bkk = tid >> 4, bj4 = (tid & 15) * 4;

    {
        float4 va = *reinterpret_cast<const float4*>(Arow);
        As[0][akk+0][amr] = va.x; As[0][akk+1][amr] = va.y;
        As[0][akk+2][amr] = va.z; As[0][akk+3][amr] = va.w;
        float4 w = *reinterpret_cast<const float4*>(&Bm[(size_t)bkk * D_MODEL + bj4]);
        Bs[0][bkk][bj4] = w.x; Bs[0][bkk][bj4+1] = w.y; Bs[0][bkk][bj4+2] = w.z; Bs[0][bkk][bj4+3] = w.w;
    }
    __syncthreads();

    unsigned long long acc[4][2] = {};
    int buf = 0;
    for (int k0 = 0; k0 < kend; k0 += 16) {
        float4 ra, rb;
        const bool more = (k0 + 16) < kend;
        if (more) {
            ra = *reinterpret_cast<const float4*>(Arow + k0 + 16);
            rb = *reinterpret_cast<const float4*>(&Bm[(size_t)(k0 + 16 + bkk) * D_MODEL + bj4]);
        }
        #pragma unroll
        for (int kk = 0; kk < 16; kk++) {
            float4 av = *reinterpret_cast<const float4*>(&As[buf][kk][ty * 4]);
            float4 bv = *reinterpret_cast<const float4*>(&Bs[buf][kk][tx * 4]);
            unsigned long long bp[2] = { pack2(bv.x, bv.y), pack2(bv.z, bv.w) };
            float a[4] = {av.x, av.y, av.z, av.w};
            #pragma unroll
            for (int i = 0; i < 4; i++) {
                unsigned long long ap = pack2(a[i], a[i]);
                ffma2(acc[i][0], ap, bp[0]);
                ffma2(acc[i][1], ap, bp[1]);
            }
        }
        if (more) {
            As[buf^1][akk+0][amr] = ra.x; As[buf^1][akk+1][amr] = ra.y;
            As[buf^1][akk+2][amr] = ra.z; As[buf^1][akk+3][amr] = ra.w;
            Bs[buf^1][bkk][bj4] = rb.x; Bs[buf^1][bkk][bj4+1] = rb.y;
            Bs[buf^1][bkk][bj4+2] = rb.z; Bs[buf^1][bkk][bj4+3] = rb.w;
            __syncthreads();
            buf ^= 1;
        }
    }
    #pragma unroll
    for (int i = 0; i < 4; i++) {
        int r = row0 + ty * 4 + i;
        float f0, f1, f2, f3;
        unpack2(acc[i][0], f0, f1);
        unpack2(acc[i][1], f2, f3);
        float* cp = &C[(size_t)r * D_MODEL + tx * 4];
        cp[0] = f0; cp[1] = f1; cp[2] = f2; cp[3] = f3;
    }
}

// ---------------------------------------------------------------------------
extern "C" void kernel_launch(void* const* d_in, const int* in_sizes, int n_in,
                              void* d_out, int out_size)
{
    const float* q   = (const float*)d_in[0];
    const float* k   = (const float*)d_in[1];
    const float* v   = (const float*)d_in[2];
    // d_in[3] = causal mask (bool) — structure known, unused
    const float* w_q = (const float*)d_in[4];
    const float* b_q = (const float*)d_in[5];
    const float* w_k = (const float*)d_in[6];
    const float* b_k = (const float*)d_in[7];
    const float* w_v = (const float*)d_in[8];
    const float* b_v = (const float*)d_in[9];
    const float* w_o = (const float*)d_in[10];
    const float* b_o = (const float*)d_in[11];
    float* out = (float*)d_out;

    const int attn_in_out = ((size_t)out_size >= OUT_ELEMS + ATTN_ELEMS) ? 1 : 0;

    dim3 thr(256);
    // Projections: [4096,1024] = X @ W^T + b  (tf32 tensor cores)
    dim3 gproj(D_MODEL / 128, MROWS / 128);
    gemm_nt_bias_tc<<<gproj, thr>>>(q, w_q, b_q, nullptr, 0, MROWS, D_MODEL, D_MODEL);
    gemm_nt_bias_tc<<<gproj, thr>>>(k, w_k, b_k, nullptr, 1, MROWS, D_MODEL, D_MODEL);
    gemm_nt_bias_tc<<<gproj, thr>>>(v, w_v, b_v, nullptr, 2, MROWS, D_MODEL, D_MODEL);

    // Scores (tf32, lower-triangle tiles only)
    dim3 gsc(SEQ / 128, SEQ / 128, BATCH * N_HEADS);
    scores_kernel_tc<<<gsc, thr>>>(out, attn_in_out);

    // Softmax (writes final attn_weights incl. exact zeros above diagonal)
    dim3 gsm(SEQ, BATCH * N_HEADS);
    softmax_kernel<<<gsm, thr>>>(out, attn_in_out);

    // attn @ V  ->  [b, s, h*64+d]
    dim3 gpv(1, SEQ / 64, BATCH * N_HEADS);
    pv_kernel<<<gpv, thr>>>(out, attn_in_out);

    // Output projection -> d_out[0 : 4M)  (tf32)
    gemm_nt_bias_tc<<<gproj, thr>>>(nullptr, w_o, b_o, out, 3, MROWS, D_MODEL, D_MODEL);
}